// round 2
// baseline (speedup 1.0000x reference)
#include <cuda_runtime.h>
#include <cuda_bf16.h>

#define NN   50000
#define NE   1200000
#define NG   64
#define FN   128
#define FE   32
#define HD   64
#define HIDD 128
#define NL   3

// ---------------- device scratch ----------------
__device__ __align__(16) float g_ea[(size_t)NE * HD];      // edge embeddings [E,64]
__device__ __align__(16) float g_h[NN * HD];               // node state
__device__ __align__(16) float g_xin[NN * HD];             // conv input (pre-norm)
__device__ __align__(16) float g_den[NN * HD];             // softmax denom accum
__device__ __align__(16) float g_wsum[NN * HD];            // weighted msg accum
__device__              unsigned int g_pool[NG * HD];      // encoded max-pool
__device__ __align__(16) float g_w1t[NL][HD][HIDD];        // conv_w1^T  [l][k][j]
__device__ __align__(16) float g_w2t[NL][HIDD][HD];        // conv_w2^T  [l][j][o]

__device__ __forceinline__ unsigned fenc(float f) {
    unsigned u = __float_as_uint(f);
    return (u & 0x80000000u) ? ~u : (u | 0x80000000u);
}
__device__ __forceinline__ float fdec(unsigned u) {
    return (u & 0x80000000u) ? __uint_as_float(u & 0x7fffffffu) : __uint_as_float(~u);
}

__device__ __forceinline__ void warp_reduce2(float& s, float& s2) {
#pragma unroll
    for (int o = 16; o > 0; o >>= 1) {
        s  += __shfl_xor_sync(0xffffffffu, s,  o);
        s2 += __shfl_xor_sync(0xffffffffu, s2, o);
    }
}

// ---------------- weight transposes ----------------
__global__ void k_transpose(const float* __restrict__ cw1, const float* __restrict__ cw2) {
    int i = blockIdx.x * blockDim.x + threadIdx.x;
    if (i < NL * HIDD * HD) {            // cw1: [L][128][64]
        int l = i / (HIDD * HD), r = i % (HIDD * HD);
        int j = r / HD, k = r % HD;
        g_w1t[l][k][j] = cw1[i];
    }
    if (i < NL * HD * HIDD) {            // cw2: [L][64][128]
        int l = i / (HD * HIDD), r = i % (HD * HIDD);
        int o = r / HIDD, j = r % HIDD;
        g_w2t[l][j][o] = cw2[i];
    }
}

// ---------------- node embedding: h = x @ ne_w^T + ne_b ----------------
__global__ void k_node_embed(const float* __restrict__ x,
                             const float* __restrict__ ne_w,
                             const float* __restrict__ ne_b) {
    __shared__ float wst[FN][HD];
    __shared__ float xsh[8][FN];
    for (int idx = threadIdx.x; idx < FN * HD; idx += blockDim.x) {
        int j = idx & (HD - 1), k = idx >> 6;
        wst[k][j] = ne_w[j * FN + k];
    }
    __syncthreads();
    int warp = threadIdx.x >> 5, lane = threadIdx.x & 31;
    int n = blockIdx.x * 8 + warp;
    if (n >= NN) return;
    ((float4*)xsh[warp])[lane] = ((const float4*)x)[(size_t)n * (FN / 4) + lane];
    __syncwarp();
    float acc0 = ne_b[lane], acc1 = ne_b[lane + 32];
#pragma unroll
    for (int k = 0; k < FN; k++) {
        float xk = xsh[warp][k];
        acc0 = fmaf(xk, wst[k][lane], acc0);
        acc1 = fmaf(xk, wst[k][lane + 32], acc1);
    }
    g_h[n * HD + lane]      = acc0;
    g_h[n * HD + lane + 32] = acc1;
}

// ---------------- edge MLP ----------------
__global__ void k_edge_mlp(const float* __restrict__ attr,
                           const float* __restrict__ w1, const float* __restrict__ b1,
                           const float* __restrict__ w2, const float* __restrict__ b2) {
    __shared__ float w1s[FE * FE];
    __shared__ float w2s[HD * FE];
    __shared__ float b1s[FE];
    __shared__ float b2s[HD];
    for (int i = threadIdx.x; i < FE * FE; i += blockDim.x) w1s[i] = w1[i];
    for (int i = threadIdx.x; i < HD * FE; i += blockDim.x) w2s[i] = w2[i];
    if (threadIdx.x < FE) b1s[threadIdx.x] = b1[threadIdx.x];
    if (threadIdx.x >= 64 && threadIdx.x < 64 + HD) b2s[threadIdx.x - 64] = b2[threadIdx.x - 64];
    __syncthreads();
    int e = blockIdx.x * blockDim.x + threadIdx.x;
    if (e >= NE) return;

    float hid[FE];
#pragma unroll
    for (int j = 0; j < FE; j++) hid[j] = b1s[j];
    const float4* in4 = (const float4*)(attr + (size_t)e * FE);
#pragma unroll
    for (int k4 = 0; k4 < FE / 4; k4++) {
        float4 v = in4[k4];
#pragma unroll
        for (int j = 0; j < FE; j++) {
            float4 w = ((const float4*)w1s)[j * (FE / 4) + k4];
            hid[j] = fmaf(v.x, w.x, fmaf(v.y, w.y, fmaf(v.z, w.z, fmaf(v.w, w.w, hid[j]))));
        }
    }
#pragma unroll
    for (int j = 0; j < FE; j++) hid[j] = fmaxf(hid[j], 0.0f);

    float4* out4 = (float4*)(g_ea + (size_t)e * HD);
#pragma unroll
    for (int i4 = 0; i4 < HD / 4; i4++) {
        float4 o = ((const float4*)b2s)[i4];
#pragma unroll
        for (int j4 = 0; j4 < FE / 4; j4++) {
            float4 wx = ((const float4*)w2s)[(i4 * 4 + 0) * (FE / 4) + j4];
            float4 wy = ((const float4*)w2s)[(i4 * 4 + 1) * (FE / 4) + j4];
            float4 wz = ((const float4*)w2s)[(i4 * 4 + 2) * (FE / 4) + j4];
            float4 ww = ((const float4*)w2s)[(i4 * 4 + 3) * (FE / 4) + j4];
            float h0 = hid[j4 * 4 + 0], h1 = hid[j4 * 4 + 1];
            float h2 = hid[j4 * 4 + 2], h3 = hid[j4 * 4 + 3];
            o.x = fmaf(h0, wx.x, fmaf(h1, wx.y, fmaf(h2, wx.z, fmaf(h3, wx.w, o.x))));
            o.y = fmaf(h0, wy.x, fmaf(h1, wy.y, fmaf(h2, wy.z, fmaf(h3, wy.w, o.y))));
            o.z = fmaf(h0, wz.x, fmaf(h1, wz.y, fmaf(h2, wz.z, fmaf(h3, wz.w, o.z))));
            o.w = fmaf(h0, ww.x, fmaf(h1, ww.y, fmaf(h2, ww.z, fmaf(h3, ww.w, o.w))));
        }
        out4[i4] = o;
    }
}

// ---------------- zero accumulators + pool ----------------
__global__ void k_zero() {
    int i = blockIdx.x * blockDim.x + threadIdx.x;
    if (i < NN * HD) { g_den[i] = 0.0f; g_wsum[i] = 0.0f; }
    if (i < NG * HD) g_pool[i] = 0u;
}

// ---------------- pre-norm: xin = relu(LN(h)); zero accums ----------------
__global__ void k_prep(const float* __restrict__ lng, const float* __restrict__ lnb, int layer) {
    int gid = blockIdx.x * blockDim.x + threadIdx.x;
    int n = gid >> 5, lane = gid & 31;
    if (n >= NN) return;
    float v0 = g_h[n * HD + lane], v1 = g_h[n * HD + lane + 32];
    float s = v0 + v1, s2 = v0 * v0 + v1 * v1;
    warp_reduce2(s, s2);
    float mu = s * (1.0f / HD);
    float var = s2 * (1.0f / HD) - mu * mu;
    float rs = rsqrtf(var + 1e-5f);
    const float* g = lng + layer * HD;
    const float* b = lnb + layer * HD;
    g_xin[n * HD + lane]      = fmaxf((v0 - mu) * rs * g[lane] + b[lane], 0.0f);
    g_xin[n * HD + lane + 32] = fmaxf((v1 - mu) * rs * g[lane + 32] + b[lane + 32], 0.0f);
    g_den[n * HD + lane] = 0.0f;     g_den[n * HD + lane + 32] = 0.0f;
    g_wsum[n * HD + lane] = 0.0f;    g_wsum[n * HD + lane + 32] = 0.0f;
}

// ---------------- single edge pass (shift-free softmax accumulation) ----------------
__global__ void k_edge_pass(int use_h, const int* __restrict__ src, const int* __restrict__ dst,
                            const float* __restrict__ ct, int layer) {
    long long gid = (long long)blockIdx.x * blockDim.x + threadIdx.x;
    int e = (int)(gid >> 4);
    if (e >= NE) return;
    int q = (int)(gid & 15);
    const float* xin = use_h ? g_h : g_xin;
    float t = __ldg(ct + layer);
    int sn = __ldg(src + e), dn = __ldg(dst + e);
    float4 ev = ((const float4*)g_ea)[(size_t)e * 16 + q];
    float4 xv = ((const float4*)xin)[(size_t)sn * 16 + q];
    float m0 = fmaxf(xv.x + ev.x, 0.0f) + 1e-7f;
    float m1 = fmaxf(xv.y + ev.y, 0.0f) + 1e-7f;
    float m2 = fmaxf(xv.z + ev.z, 0.0f) + 1e-7f;
    float m3 = fmaxf(xv.w + ev.w, 0.0f) + 1e-7f;
    float a0 = __expf(m0 * t), a1 = __expf(m1 * t);
    float a2 = __expf(m2 * t), a3 = __expf(m3 * t);
    float* dp = g_den  + (size_t)dn * HD + q * 4;
    float* wp = g_wsum + (size_t)dn * HD + q * 4;
    asm volatile("red.global.add.v4.f32 [%0], {%1,%2,%3,%4};"
                 :: "l"(dp), "f"(a0), "f"(a1), "f"(a2), "f"(a3) : "memory");
    asm volatile("red.global.add.v4.f32 [%0], {%1,%2,%3,%4};"
                 :: "l"(wp), "f"(m0 * a0), "f"(m1 * a1), "f"(m2 * a2), "f"(m3 * a3) : "memory");
}

// ---------------- node update: agg/residual + MLP(64->128->LN->relu->64) ----------------
__global__ void k_node_update(int use_h,
                              const float* __restrict__ cb1, const float* __restrict__ cg,
                              const float* __restrict__ cbn, const float* __restrict__ cb2,
                              int layer, int resid) {
    __shared__ float xs[8][HD];
    __shared__ float vs[8][HIDD];
    int warp = threadIdx.x >> 5, lane = threadIdx.x & 31;
    int n = blockIdx.x * 8 + warp;
    if (n >= NN) return;
    const float* xin = use_h ? g_h : g_xin;
    float4 b1v = ((const float4*)(cb1 + layer * HIDD))[lane];
    float4 gv  = ((const float4*)(cg  + layer * HIDD))[lane];
    float4 bv  = ((const float4*)(cbn + layer * HIDD))[lane];
    float2 b2v = ((const float2*)(cb2 + layer * HD))[lane];
    int base = n * HD;

    float o0 = g_wsum[base + lane]      / (g_den[base + lane]      + 1e-16f) + xin[base + lane];
    float o1 = g_wsum[base + lane + 32] / (g_den[base + lane + 32] + 1e-16f) + xin[base + lane + 32];
    xs[warp][lane] = o0; xs[warp][lane + 32] = o1;
    __syncwarp();

    const float4* w1r = (const float4*)g_w1t[layer];
    float4 acc = b1v;
#pragma unroll
    for (int k = 0; k < HD; k++) {
        float xk = xs[warp][k];
        float4 w = w1r[k * (HIDD / 4) + lane];
        acc.x = fmaf(xk, w.x, acc.x);
        acc.y = fmaf(xk, w.y, acc.y);
        acc.z = fmaf(xk, w.z, acc.z);
        acc.w = fmaf(xk, w.w, acc.w);
    }
    float s = acc.x + acc.y + acc.z + acc.w;
    float s2 = acc.x * acc.x + acc.y * acc.y + acc.z * acc.z + acc.w * acc.w;
    warp_reduce2(s, s2);
    float mu = s * (1.0f / HIDD);
    float var = s2 * (1.0f / HIDD) - mu * mu;
    float rs = rsqrtf(var + 1e-5f);
    float4 v;
    v.x = fmaxf((acc.x - mu) * rs * gv.x + bv.x, 0.0f);
    v.y = fmaxf((acc.y - mu) * rs * gv.y + bv.y, 0.0f);
    v.z = fmaxf((acc.z - mu) * rs * gv.z + bv.z, 0.0f);
    v.w = fmaxf((acc.w - mu) * rs * gv.w + bv.w, 0.0f);
    ((float4*)vs[warp])[lane] = v;
    __syncwarp();

    const float2* w2r = (const float2*)g_w2t[layer];
    float2 acc2 = b2v;
#pragma unroll
    for (int j = 0; j < HIDD; j++) {
        float vj = vs[warp][j];
        float2 w = w2r[j * (HD / 2) + lane];
        acc2.x = fmaf(vj, w.x, acc2.x);
        acc2.y = fmaf(vj, w.y, acc2.y);
    }
    float2* hp = (float2*)(g_h + base) + lane;
    if (resid) { float2 hv = *hp; acc2.x += hv.x; acc2.y += hv.y; }
    *hp = acc2;
}

// ---------------- final norm + global max pool ----------------
__global__ void k_final_pool(const float* __restrict__ lng, const float* __restrict__ lnb,
                             const int* __restrict__ batch) {
    int gid = blockIdx.x * blockDim.x + threadIdx.x;
    int n = gid >> 5, lane = gid & 31;
    if (n >= NN) return;
    float v0 = g_h[n * HD + lane], v1 = g_h[n * HD + lane + 32];
    float s = v0 + v1, s2 = v0 * v0 + v1 * v1;
    warp_reduce2(s, s2);
    float mu = s * (1.0f / HD);
    float var = s2 * (1.0f / HD) - mu * mu;
    float rs = rsqrtf(var + 1e-5f);
    float z0 = fmaxf((v0 - mu) * rs * lng[lane] + lnb[lane], 0.0f);
    float z1 = fmaxf((v1 - mu) * rs * lng[lane + 32] + lnb[lane + 32], 0.0f);
    int g = __ldg(batch + n);
    atomicMax(&g_pool[g * HD + lane],      fenc(z0));
    atomicMax(&g_pool[g * HD + lane + 32], fenc(z1));
}

// ---------------- readout: sigmoid(pool @ ro_w^T + ro_b) ----------------
__global__ void k_readout(const float* __restrict__ ro_w, const float* __restrict__ ro_b,
                          float* __restrict__ out) {
    int g = threadIdx.x;
    if (g >= NG) return;
    float acc = ro_b[0];
#pragma unroll
    for (int f = 0; f < HD; f++)
        acc = fmaf(fdec(g_pool[g * HD + f]), ro_w[f], acc);
    out[g] = 1.0f / (1.0f + expf(-acc));
}

extern "C" void kernel_launch(void* const* d_in, const int* in_sizes, int n_in,
                              void* d_out, int out_size) {
    const float* x       = (const float*)d_in[0];
    const float* eattr   = (const float*)d_in[1];
    const float* ne_w    = (const float*)d_in[2];
    const float* ne_b    = (const float*)d_in[3];
    const float* ee_w1   = (const float*)d_in[4];
    const float* ee_b1   = (const float*)d_in[5];
    const float* ee_w2   = (const float*)d_in[6];
    const float* ee_b2   = (const float*)d_in[7];
    const float* conv_w1 = (const float*)d_in[8];
    const float* conv_b1 = (const float*)d_in[9];
    const float* conv_g  = (const float*)d_in[10];
    const float* conv_bn = (const float*)d_in[11];
    const float* conv_w2 = (const float*)d_in[12];
    const float* conv_b2 = (const float*)d_in[13];
    const float* conv_t  = (const float*)d_in[14];
    const float* ln_g    = (const float*)d_in[15];
    const float* ln_b    = (const float*)d_in[16];
    const float* ro_w    = (const float*)d_in[17];
    const float* ro_b    = (const float*)d_in[18];
    const int*   eidx    = (const int*)d_in[19];
    const int*   batch   = (const int*)d_in[20];
    const int* src = eidx;
    const int* dst = eidx + NE;
    float* out = (float*)d_out;

    k_transpose<<<(NL * HIDD * HD + 255) / 256, 256>>>(conv_w1, conv_w2);
    k_node_embed<<<(NN + 7) / 8, 256>>>(x, ne_w, ne_b);
    k_edge_mlp<<<(NE + 255) / 256, 256>>>(eattr, ee_w1, ee_b1, ee_w2, ee_b2);
    k_zero<<<(NN * HD + 255) / 256, 256>>>();

    // layer 0 (conv on raw h)
    k_edge_pass<<<(int)(((long long)NE * 16 + 255) / 256), 256>>>(1, src, dst, conv_t, 0);
    k_node_update<<<(NN + 7) / 8, 256>>>(1, conv_b1, conv_g, conv_bn, conv_b2, 0, 0);

    // layers 1..2: norm->relu->conv->residual
    for (int l = 1; l < NL; l++) {
        k_prep<<<(NN * 32 + 255) / 256, 256>>>(ln_g, ln_b, l);
        k_edge_pass<<<(int)(((long long)NE * 16 + 255) / 256), 256>>>(0, src, dst, conv_t, l);
        k_node_update<<<(NN + 7) / 8, 256>>>(0, conv_b1, conv_g, conv_bn, conv_b2, l, 1);
    }

    k_final_pool<<<(NN * 32 + 255) / 256, 256>>>(ln_g, ln_b, batch);
    k_readout<<<1, 64>>>(ro_w, ro_b, out);
}